// round 3
// baseline (speedup 1.0000x reference)
#include <cuda_runtime.h>
#include <cuda_bf16.h>

#define BATCH  64
#define NPTS   1024
#define CHUNKS 16
#define JCHUNK (NPTS / CHUNKS)   // 64 j-values per block
#define TPB    256               // threads per block; each owns 4 shifts
#define SPT    4                 // shifts per thread (TPB*SPT == NPTS)

// Deterministic scratch (no atomics, no allocations).
__device__ float g_partial[CHUNKS][BATCH][NPTS];  // 4 MB
__device__ float g_min[BATCH];

// ---- packed f32x2 helpers (ptxas will not auto-fuse; must be PTX) ----------
__device__ __forceinline__ unsigned long long pk2(float a, float b) {
    unsigned long long r;
    asm("mov.b64 %0, {%1, %2};" : "=l"(r) : "f"(a), "f"(b));
    return r;
}
__device__ __forceinline__ void upk2(unsigned long long v, float& a, float& b) {
    asm("mov.b64 {%0, %1}, %2;" : "=f"(a), "=f"(b) : "l"(v));
}
__device__ __forceinline__ unsigned long long addx2(unsigned long long a,
                                                    unsigned long long b) {
    unsigned long long r;
    asm("add.rn.f32x2 %0, %1, %2;" : "=l"(r) : "l"(a), "l"(b));
    return r;
}
__device__ __forceinline__ unsigned long long mulx2(unsigned long long a,
                                                    unsigned long long b) {
    unsigned long long r;
    asm("mul.rn.f32x2 %0, %1, %2;" : "=l"(r) : "l"(a), "l"(b));
    return r;
}
__device__ __forceinline__ float sqrt_approx(float x) {
    float r;
    asm("sqrt.approx.f32 %0, %1;" : "=f"(r) : "f"(x));
    return r;
}

// ---------------------------------------------------------------------------
// Kernel 1: partial shift sums.
// Grid: (CHUNKS, BATCH), TPB=256 threads; thread t owns shifts t, t+256, t+512, t+768.
// shift_sum[b][s] += sum_{j in chunk} || x[b][j] - target[b][(j - s) mod N] ||
// Target is duplicated (2N, pre-NEGATED) in smem: mod -> linear index, diff -> packed add.
// ---------------------------------------------------------------------------
__global__ void __launch_bounds__(TPB, 6)
snake_main_kernel(const float2* __restrict__ x, const float2* __restrict__ tg)
{
    __shared__ unsigned long long tdup[2 * NPTS];   // 16 KB, holds (-tx, -ty)
    __shared__ float4 xs4[JCHUNK / 2];              // 512 B, x points in pairs

    const int b     = blockIdx.y;
    const int chunk = blockIdx.x;
    const int j0    = chunk * JCHUNK;
    const int t     = threadIdx.x;

    const float2* __restrict__ tb = tg + b * NPTS;
    const float2* __restrict__ xb = x  + b * NPTS;

    // Fill duplicated negated target (4 points/thread) and x chunk pairs.
    #pragma unroll
    for (int i = t; i < NPTS; i += TPB) {
        float2 tv = tb[i];
        unsigned long long p = pk2(-tv.x, -tv.y);
        tdup[i]        = p;
        tdup[i + NPTS] = p;
    }
    if (t < JCHUNK / 2)
        xs4[t] = *(const float4*)(xb + j0 + 2 * t);
    __syncthreads();

    // tv index for shift s at offset jj: j0 + jj + NPTS - s  (always in [1, 2N-1])
    int base0 = j0 + NPTS - t;
    unsigned long long acc0 = 0, acc1 = 0, acc2 = 0, acc3 = 0;

    #pragma unroll 4
    for (int jj = 0; jj < JCHUNK; jj += 2) {
        float4 xq = xs4[jj >> 1];                    // LDS.128 broadcast: 2 points
        unsigned long long xv0 = pk2(xq.x, xq.y);
        unsigned long long xv1 = pk2(xq.z, xq.w);

        #pragma unroll
        for (int k = 0; k < SPT; ++k) {
            const int bs = base0 - k * TPB + jj;     // shift s = t + k*256
            unsigned long long t0 = tdup[bs];        // LDS.64, coalesced
            unsigned long long t1 = tdup[bs + 1];

            unsigned long long d0 = addx2(xv0, t0);  // (dx,dy) in one op
            unsigned long long d1 = addx2(xv1, t1);
            unsigned long long q0 = mulx2(d0, d0);   // (dx^2,dy^2)
            unsigned long long q1 = mulx2(d1, d1);

            float a0, b0f, a1, b1f;
            upk2(q0, a0, b0f);
            upk2(q1, a1, b1f);
            float r0 = sqrt_approx(a0 + b0f);
            float r1 = sqrt_approx(a1 + b1f);

            unsigned long long dpair = pk2(r0, r1);
            switch (k) {                              // packed accumulate
                case 0: acc0 = addx2(acc0, dpair); break;
                case 1: acc1 = addx2(acc1, dpair); break;
                case 2: acc2 = addx2(acc2, dpair); break;
                case 3: acc3 = addx2(acc3, dpair); break;
            }
        }
    }

    float lo, hi;
    upk2(acc0, lo, hi); g_partial[chunk][b][t          ] = lo + hi;
    upk2(acc1, lo, hi); g_partial[chunk][b][t + TPB    ] = lo + hi;
    upk2(acc2, lo, hi); g_partial[chunk][b][t + 2 * TPB] = lo + hi;
    upk2(acc3, lo, hi); g_partial[chunk][b][t + 3 * TPB] = lo + hi;
}

// ---------------------------------------------------------------------------
// Kernel 2: per-batch reduce. Grid: (BATCH), 1024 threads.
// Sum partials over chunks (fixed order), then block-min over the 1024 shifts.
// ---------------------------------------------------------------------------
__global__ void __launch_bounds__(1024)
snake_reduce_kernel(void)
{
    const int b = blockIdx.x;
    const int s = threadIdx.x;

    float sum = 0.0f;
    #pragma unroll
    for (int c = 0; c < CHUNKS; ++c)
        sum += g_partial[c][b][s];

    float v = sum;
    #pragma unroll
    for (int o = 16; o > 0; o >>= 1)
        v = fminf(v, __shfl_xor_sync(0xFFFFFFFFu, v, o));

    __shared__ float warpmin[32];
    if ((threadIdx.x & 31) == 0) warpmin[threadIdx.x >> 5] = v;
    __syncthreads();

    if (threadIdx.x < 32) {
        v = warpmin[threadIdx.x];
        #pragma unroll
        for (int o = 16; o > 0; o >>= 1)
            v = fminf(v, __shfl_xor_sync(0xFFFFFFFFu, v, o));
        if (threadIdx.x == 0) g_min[b] = v;   // min of raw sums; /N folded below
    }
}

// ---------------------------------------------------------------------------
// Kernel 3: final mean over batch. 1 block, 32 threads.
// ---------------------------------------------------------------------------
__global__ void snake_final_kernel(float* __restrict__ out)
{
    float v = g_min[threadIdx.x] + g_min[threadIdx.x + 32];
    #pragma unroll
    for (int o = 16; o > 0; o >>= 1)
        v += __shfl_xor_sync(0xFFFFFFFFu, v, o);
    if (threadIdx.x == 0)
        out[0] = v * (1.0f / (float)(BATCH * NPTS));
}

// ---------------------------------------------------------------------------
extern "C" void kernel_launch(void* const* d_in, const int* in_sizes, int n_in,
                              void* d_out, int out_size)
{
    const float2* x  = (const float2*)d_in[0];
    const float2* tg = (const float2*)d_in[1];
    float* out = (float*)d_out;

    dim3 grid(CHUNKS, BATCH);
    snake_main_kernel<<<grid, TPB>>>(x, tg);
    snake_reduce_kernel<<<BATCH, 1024>>>();
    snake_final_kernel<<<1, 32>>>(out);
}

// round 4
// speedup vs baseline: 1.0714x; 1.0714x over previous
#include <cuda_runtime.h>
#include <cuda_bf16.h>

#define BATCH  64
#define NPTS   1024
#define CHUNKS 32
#define JCH    (NPTS / CHUNKS)      // 32 j per block
#define NJP    (JCH / 2)            // 16 j-pairs
#define TPB    256
#define SPT    4                    // consecutive shifts per thread

// Deterministic scratch (no atomics, no allocations).
__device__ float g_partial[CHUNKS][BATCH][NPTS];  // 8 MB
__device__ float g_min[BATCH];

typedef unsigned long long u64;

// ---- packed f32x2 helpers ---------------------------------------------------
__device__ __forceinline__ u64 pk2(float a, float b) {
    u64 r; asm("mov.b64 %0, {%1, %2};" : "=l"(r) : "f"(a), "f"(b)); return r;
}
__device__ __forceinline__ void upk2(u64 v, float& a, float& b) {
    asm("mov.b64 {%0, %1}, %2;" : "=f"(a), "=f"(b) : "l"(v));
}
__device__ __forceinline__ u64 addx2(u64 a, u64 b) {
    u64 r; asm("add.rn.f32x2 %0, %1, %2;" : "=l"(r) : "l"(a), "l"(b)); return r;
}
__device__ __forceinline__ u64 mulx2(u64 a, u64 b) {
    u64 r; asm("mul.rn.f32x2 %0, %1, %2;" : "=l"(r) : "l"(a), "l"(b)); return r;
}
__device__ __forceinline__ u64 fmx2(u64 a, u64 b, u64 c) {
    u64 r; asm("fma.rn.f32x2 %0, %1, %2, %3;" : "=l"(r) : "l"(a), "l"(b), "l"(c)); return r;
}
__device__ __forceinline__ float sqrtapx(float x) {
    float r; asm("sqrt.approx.f32 %0, %1;" : "=f"(r) : "f"(x)); return r;
}

// ---------------------------------------------------------------------------
// Kernel 1: partial shift sums.
// Grid (CHUNKS, BATCH), TPB=256. Thread t owns shifts 4t..4t+3, walks the
// chunk's j values in pairs. SoA negated target duplicated in smem; a sliding
// 3-pair register window (C,A,B per coordinate) gives all 4 shift alignments
// from ONE new LDS.64 per coordinate per j-pair.
//   shift s=4t+m, pair (j,j+1):  target idx (e-m, e+1-m),  e = j - 4t + N
//   m=0:(B.lo,B.hi)  m=1:(A.hi,B.lo)  m=2:(A.lo,A.hi)  m=3:(C.hi,A.lo)
// ---------------------------------------------------------------------------
__global__ void __launch_bounds__(TPB, 5)
snake_main_kernel(const float2* __restrict__ x, const float2* __restrict__ tg)
{
    __shared__ __align__(16) float TXs[2 * NPTS];  // -t.x duplicated, 8 KB
    __shared__ __align__(16) float TYs[2 * NPTS];  // -t.y duplicated, 8 KB
    __shared__ u64 XPX[NJP];                       // (x_j.x, x_{j+1}.x)
    __shared__ u64 XPY[NJP];                       // (x_j.y, x_{j+1}.y)

    const int b     = blockIdx.y;
    const int chunk = blockIdx.x;
    const int j0    = chunk * JCH;
    const int t     = threadIdx.x;

    const float2* __restrict__ tb = tg + b * NPTS;
    const float2* __restrict__ xb = x  + b * NPTS;

    #pragma unroll
    for (int i = t; i < 2 * NPTS; i += TPB) {
        float2 tv = tb[i & (NPTS - 1)];
        TXs[i] = -tv.x;
        TYs[i] = -tv.y;
    }
    if (t < NJP) {
        float4 q = *(const float4*)(xb + j0 + 2 * t);   // (xj.x,xj.y,xj1.x,xj1.y)
        XPX[t] = pk2(q.x, q.z);
        XPY[t] = pk2(q.y, q.w);
    }
    __syncthreads();

    const int s0 = SPT * t;                 // first shift owned by this thread
    const int e0 = j0 - s0 + NPTS;          // e for jj=0 (even, >= 4)

    // Scalar accumulators: acc[m] pair summed at the end. Fixed order -> deterministic.
    float a00=0,a01=0,a10=0,a11=0,a20=0,a21=0,a30=0,a31=0;

    // Preload window: C=(e0-4,e0-3), A=(e0-2,e0-1) per coordinate.
    float2 cx = *(const float2*)&TXs[e0 - 4];
    float2 ax = *(const float2*)&TXs[e0 - 2];
    float2 cy = *(const float2*)&TYs[e0 - 4];
    float2 ay = *(const float2*)&TYs[e0 - 2];

    #pragma unroll
    for (int jj = 0; jj < NJP; ++jj) {
        const int e = e0 + 2 * jj;
        float2 bx = *(const float2*)&TXs[e];   // LDS.64, new pair
        float2 by = *(const float2*)&TYs[e];
        u64 xpx = XPX[jj];                     // broadcast LDS.64
        u64 xpy = XPY[jj];

        // shift-aligned target pairs (negated)
        u64 tx0 = pk2(bx.x, bx.y);
        u64 tx1 = pk2(ax.y, bx.x);
        u64 tx2 = pk2(ax.x, ax.y);
        u64 tx3 = pk2(cx.y, ax.x);
        u64 ty0 = pk2(by.x, by.y);
        u64 ty1 = pk2(ay.y, by.x);
        u64 ty2 = pk2(ay.x, ay.y);
        u64 ty3 = pk2(cy.y, ay.x);

        {   // m = 0
            u64 dx = addx2(xpx, tx0), dy = addx2(xpy, ty0);
            u64 d2 = fmx2(dy, dy, mulx2(dx, dx));
            float lo, hi; upk2(d2, lo, hi);
            a00 += sqrtapx(lo); a01 += sqrtapx(hi);
        }
        {   // m = 1
            u64 dx = addx2(xpx, tx1), dy = addx2(xpy, ty1);
            u64 d2 = fmx2(dy, dy, mulx2(dx, dx));
            float lo, hi; upk2(d2, lo, hi);
            a10 += sqrtapx(lo); a11 += sqrtapx(hi);
        }
        {   // m = 2
            u64 dx = addx2(xpx, tx2), dy = addx2(xpy, ty2);
            u64 d2 = fmx2(dy, dy, mulx2(dx, dx));
            float lo, hi; upk2(d2, lo, hi);
            a20 += sqrtapx(lo); a21 += sqrtapx(hi);
        }
        {   // m = 3
            u64 dx = addx2(xpx, tx3), dy = addx2(xpy, ty3);
            u64 d2 = fmx2(dy, dy, mulx2(dx, dx));
            float lo, hi; upk2(d2, lo, hi);
            a30 += sqrtapx(lo); a31 += sqrtapx(hi);
        }

        // rotate window (register renaming under full unroll, no MOVs)
        cx = ax; ax = bx;
        cy = ay; ay = by;
    }

    g_partial[chunk][b][s0 + 0] = a00 + a01;
    g_partial[chunk][b][s0 + 1] = a10 + a11;
    g_partial[chunk][b][s0 + 2] = a20 + a21;
    g_partial[chunk][b][s0 + 3] = a30 + a31;
}

// ---------------------------------------------------------------------------
// Kernel 2: per-batch reduce. Grid: (BATCH), 1024 threads.
// Sum partials over chunks (fixed order), then block-min over the 1024 shifts.
// ---------------------------------------------------------------------------
__global__ void __launch_bounds__(1024)
snake_reduce_kernel(void)
{
    const int b = blockIdx.x;
    const int s = threadIdx.x;

    float sum = 0.0f;
    #pragma unroll
    for (int c = 0; c < CHUNKS; ++c)
        sum += g_partial[c][b][s];

    float v = sum;
    #pragma unroll
    for (int o = 16; o > 0; o >>= 1)
        v = fminf(v, __shfl_xor_sync(0xFFFFFFFFu, v, o));

    __shared__ float warpmin[32];
    if ((threadIdx.x & 31) == 0) warpmin[threadIdx.x >> 5] = v;
    __syncthreads();

    if (threadIdx.x < 32) {
        v = warpmin[threadIdx.x];
        #pragma unroll
        for (int o = 16; o > 0; o >>= 1)
            v = fminf(v, __shfl_xor_sync(0xFFFFFFFFu, v, o));
        if (threadIdx.x == 0) g_min[b] = v;   // min of raw sums; /N folded below
    }
}

// ---------------------------------------------------------------------------
// Kernel 3: final mean over batch. 1 block, 32 threads.
// ---------------------------------------------------------------------------
__global__ void snake_final_kernel(float* __restrict__ out)
{
    float v = g_min[threadIdx.x] + g_min[threadIdx.x + 32];
    #pragma unroll
    for (int o = 16; o > 0; o >>= 1)
        v += __shfl_xor_sync(0xFFFFFFFFu, v, o);
    if (threadIdx.x == 0)
        out[0] = v * (1.0f / (float)(BATCH * NPTS));
}

// ---------------------------------------------------------------------------
extern "C" void kernel_launch(void* const* d_in, const int* in_sizes, int n_in,
                              void* d_out, int out_size)
{
    const float2* x  = (const float2*)d_in[0];
    const float2* tg = (const float2*)d_in[1];
    float* out = (float*)d_out;

    dim3 grid(CHUNKS, BATCH);
    snake_main_kernel<<<grid, TPB>>>(x, tg);
    snake_reduce_kernel<<<BATCH, 1024>>>();
    snake_final_kernel<<<1, 32>>>(out);
}